// round 15
// baseline (speedup 1.0000x reference)
#include <cuda_runtime.h>
#include <cuda_bf16.h>
#include <cstdint>

#define BB 8
#define NN 2048
#define ITERS 50

// ---- device scratch (no allocs allowed) ----
__device__ float gE[BB * 16384], gE2[BB * 16384], gS[BB * 16384];
__device__ __nv_bfloat16 gW1[BB * 16384], gW2[BB * 16384];

// ---- f32x2 helpers (prep kernels) ----
__device__ __forceinline__ unsigned long long ffma2(unsigned long long a,
                                                    unsigned long long b,
                                                    unsigned long long c) {
    unsigned long long d;
    asm("fma.rn.f32x2 %0, %1, %2, %3;" : "=l"(d) : "l"(a), "l"(b), "l"(c));
    return d;
}
__device__ __forceinline__ unsigned long long pack2(float x) {
    union { unsigned long long u; float2 f; } c; c.f = make_float2(x, x); return c.u;
}
__device__ __forceinline__ float2 unpack2(unsigned long long v) {
    union { unsigned long long u; float2 f; } c; c.u = v; return c.f;
}

// ---- HMMA m16n8k16 bf16 -> f32 ----
__device__ __forceinline__ void mma_bf16(float c[4],
                                         uint32_t a0, uint32_t a1, uint32_t a2, uint32_t a3,
                                         uint32_t b0, uint32_t b1) {
    asm volatile(
        "mma.sync.aligned.m16n8k16.row.col.f32.bf16.bf16.f32 "
        "{%0,%1,%2,%3}, {%4,%5,%6,%7}, {%8,%9}, {%0,%1,%2,%3};"
        : "+f"(c[0]), "+f"(c[1]), "+f"(c[2]), "+f"(c[3])
        : "r"(a0), "r"(a1), "r"(a2), "r"(a3), "r"(b0), "r"(b1));
}

__device__ __forceinline__ void split2(float x, float y, uint32_t& hi, uint32_t& lo) {
    __nv_bfloat162 h = __float22bfloat162_rn(make_float2(x, y));
    float2 hb = __bfloat1622float2(h);
    __nv_bfloat162 l = __float22bfloat162_rn(make_float2(x - hb.x, y - hb.y));
    hi = *(uint32_t*)&h;
    lo = *(uint32_t*)&l;
}

__device__ __forceinline__ void barg128(int id) {
    asm volatile("bar.sync %0, %1;" :: "r"(id), "r"(128) : "memory");
}

// ============================================================================
// kE: E = (1/8192) V V^T.  grid 64 x 256.
// ============================================================================
__global__ __launch_bounds__(256, 1) void kE(const float* __restrict__ gV) {
    extern __shared__ float sm[];
    float* sVt = sm;                         // [128][132]
    const int b = blockIdx.x >> 3, r0 = (blockIdx.x & 7) * 16;
    const int t = threadIdx.x;
    for (int idx = t; idx < 16384; idx += 256) {
        int m = idx >> 7, d = idx & 127;
        sVt[d * 132 + m] = gV[b * 16384 + idx];
    }
    __syncthreads();
    const int r = r0 + (t & 15), i0 = (t >> 4) * 8;
    unsigned long long acc[4];
#pragma unroll
    for (int e = 0; e < 4; e++) acc[e] = 0ULL;
#pragma unroll 8
    for (int d = 0; d < 128; d++) {
        unsigned long long a2 = pack2(sVt[d * 132 + r]);
        const ulonglong2* pm = (const ulonglong2*)(sVt + d * 132 + i0);
        ulonglong2 m0 = pm[0], m1 = pm[1];
        acc[0] = ffma2(m0.x, a2, acc[0]);
        acc[1] = ffma2(m0.y, a2, acc[1]);
        acc[2] = ffma2(m1.x, a2, acc[2]);
        acc[3] = ffma2(m1.y, a2, acc[3]);
    }
    const float sc = 1.0f / 8192.0f;
#pragma unroll
    for (int e = 0; e < 4; e++) {
        float2 v = unpack2(acc[e]);
        gE[b * 16384 + r * 128 + i0 + 2 * e]     = sc * v.x;
        gE[b * 16384 + r * 128 + i0 + 2 * e + 1] = sc * v.y;
    }
}

// ============================================================================
// kMM1: E2 = E*E ; S = I - E + E2.   grid 128 x 256.
// ============================================================================
__global__ __launch_bounds__(256, 1) void kMM1() {
    extern __shared__ float sm[];
    float* sA = sm;                 // E slice [8][129]
    float* sB = sm + 8 * 129;       // E full [128][128]
    const int b = blockIdx.x >> 4, r0 = (blockIdx.x & 15) * 8;
    const int t = threadIdx.x;
    for (int idx = t; idx < 1024; idx += 256) {
        int row = idx >> 7, j = idx & 127;
        sA[row * 129 + j] = gE[b * 16384 + (r0 + row) * 128 + j];
    }
    for (int idx = t; idx < 4096; idx += 256)
        ((float4*)sB)[idx] = ((const float4*)(gE + b * 16384))[idx];
    __syncthreads();
    const int rl = t & 7, r = r0 + rl, i0 = (t >> 3) * 4;
    unsigned long long acc[2];
    acc[0] = 0ULL; acc[1] = 0ULL;
#pragma unroll 8
    for (int j = 0; j < 128; j++) {
        unsigned long long a2 = pack2(sA[rl * 129 + j]);
        ulonglong2 mv = *(const ulonglong2*)(sB + j * 128 + i0);
        acc[0] = ffma2(mv.x, a2, acc[0]);
        acc[1] = ffma2(mv.y, a2, acc[1]);
    }
#pragma unroll
    for (int e = 0; e < 2; e++) {
        float2 v = unpack2(acc[e]);
        int c0 = i0 + 2 * e;
        gE2[b * 16384 + r * 128 + c0]     = v.x;
        gE2[b * 16384 + r * 128 + c0 + 1] = v.y;
        gS[b * 16384 + r * 128 + c0]     = ((r == c0)     ? 1.0f : 0.0f) - sA[rl * 129 + c0]     + v.x;
        gS[b * 16384 + r * 128 + c0 + 1] = ((r == c0 + 1) ? 1.0f : 0.0f) - sA[rl * 129 + c0 + 1] + v.y;
    }
}

// ============================================================================
// kMM2: W = E2*S - E  (deg-4 Neumann; trunc ~1e-6) -> bf16 hi/lo.  grid 128 x 256.
// ============================================================================
__global__ __launch_bounds__(256, 1) void kMM2() {
    extern __shared__ float sm[];
    float* sA = sm;                 // E2 slice [8][129]
    float* sE = sm + 8 * 129;       // E slice  [8][129]
    float* sB = sm + 16 * 129;      // S full [128][128]
    const int b = blockIdx.x >> 4, r0 = (blockIdx.x & 15) * 8;
    const int t = threadIdx.x;
    for (int idx = t; idx < 1024; idx += 256) {
        int row = idx >> 7, j = idx & 127;
        sA[row * 129 + j] = gE2[b * 16384 + (r0 + row) * 128 + j];
        sE[row * 129 + j] = gE [b * 16384 + (r0 + row) * 128 + j];
    }
    for (int idx = t; idx < 4096; idx += 256)
        ((float4*)sB)[idx] = ((const float4*)(gS + b * 16384))[idx];
    __syncthreads();
    const int rl = t & 7, r = r0 + rl, k0 = (t >> 3) * 4;
    unsigned long long acc[2];
    acc[0] = 0ULL; acc[1] = 0ULL;
#pragma unroll 8
    for (int j = 0; j < 128; j++) {
        unsigned long long a2 = pack2(sA[rl * 129 + j]);
        ulonglong2 mv = *(const ulonglong2*)(sB + j * 128 + k0);
        acc[0] = ffma2(mv.x, a2, acc[0]);
        acc[1] = ffma2(mv.y, a2, acc[1]);
    }
    uint32_t* o1 = (uint32_t*)gW1 + b * 8192;
    uint32_t* o2 = (uint32_t*)gW2 + b * 8192;
#pragma unroll
    for (int e = 0; e < 2; e++) {
        float2 tv = unpack2(acc[e]);
        int k = k0 + 2 * e;
        float wx = tv.x - sE[rl * 129 + k];
        float wy = tv.y - sE[rl * 129 + k + 1];
        uint32_t hi, lo;
        split2(wx, wy, hi, lo);
        o1[r * 64 + (k >> 1)] = hi;
        o2[r * 64 + (k >> 1)] = lo;
    }
}

// ============================================================================
// k_admm: fused P-prep + 50 HMMA ADMM iters + epilogue.
// rhs tiles stored k-packed: word p (=col/2) at q=(p&7)*8+(p>>3), row stride
// 68 u32 -> A-fragment loads become LDS.64 covering 2 k-steps (64 vs 128
// loads/warp/iter). P in smem (reg headroom), single rhs buffer, 2 bars/iter.
// Values + MMA order bit-identical to R12 (k0 asc; Ah*W1, Al*W1, Ah*W2).
// 4 independent 128-thread groups (rows 32g..32g+31).
// SMEM budget: sCnt is [128][16] f32 = 8192 B (R14 bug: was sized 4096 -> OOB).
// ============================================================================
#define S136 136
#define SU 68
#define SM_RH 0                  // rhs hi, u32 [128][68] = 34816 B
#define SM_RL 34816
#define SM_W1 69632              // W hi bf16 [128][136] (V hi prologue / Vt hi epilogue)
#define SM_W2 104448
#define SM_P  139264             // f32 [128][132] = 67584
#define SM_CNT 206848            // f32 [128][16] = 8192
#define SMEM_ADMM 215040

__device__ __forceinline__ int qperm(int p) { return ((p & 7) << 3) | (p >> 3); }

// 3-term split GEMM; A via LDS.64 from k-packed tiles, B scalar from S136 W.
__device__ __forceinline__ void gemm3(float acc[2][4][4],
                                      const uint32_t* __restrict__ rhU,
                                      const uint32_t* __restrict__ rlU,
                                      const __nv_bfloat16* __restrict__ w1B,
                                      const __nv_bfloat16* __restrict__ w2B,
                                      int rA, int n0, int tig, int gid) {
#pragma unroll
    for (int kc = 0; kc < 4; kc++) {
        uint2 Ah[2][2][2], Al[2][2][2];   // [mt][rowhalf][res]
#pragma unroll
        for (int mt = 0; mt < 2; mt++)
#pragma unroll
            for (int rh = 0; rh < 2; rh++) {
                int row = rA + 16 * mt + 8 * rh;
                Ah[mt][rh][0] = *(const uint2*)(rhU + row * SU + tig * 8 + 2 * kc);
                Ah[mt][rh][1] = *(const uint2*)(rhU + row * SU + (tig + 4) * 8 + 2 * kc);
                Al[mt][rh][0] = *(const uint2*)(rlU + row * SU + tig * 8 + 2 * kc);
                Al[mt][rh][1] = *(const uint2*)(rlU + row * SU + (tig + 4) * 8 + 2 * kc);
            }
#pragma unroll
        for (int kk = 0; kk < 2; kk++) {
            int ka = (kc * 2 + kk) * 16 + 2 * tig;
#pragma unroll
            for (int nt = 0; nt < 4; nt++) {
                int bn = n0 + nt * 8 + gid;
                uint32_t b0 = *(const uint32_t*)(w1B + bn * S136 + ka);
                uint32_t b1 = *(const uint32_t*)(w1B + bn * S136 + ka + 8);
                uint32_t c0 = *(const uint32_t*)(w2B + bn * S136 + ka);
                uint32_t c1 = *(const uint32_t*)(w2B + bn * S136 + ka + 8);
#pragma unroll
                for (int mt = 0; mt < 2; mt++) {
                    uint32_t a0 = kk ? Ah[mt][0][0].y : Ah[mt][0][0].x;
                    uint32_t a1 = kk ? Ah[mt][1][0].y : Ah[mt][1][0].x;
                    uint32_t a2 = kk ? Ah[mt][0][1].y : Ah[mt][0][1].x;
                    uint32_t a3 = kk ? Ah[mt][1][1].y : Ah[mt][1][1].x;
                    uint32_t l0 = kk ? Al[mt][0][0].y : Al[mt][0][0].x;
                    uint32_t l1 = kk ? Al[mt][1][0].y : Al[mt][1][0].x;
                    uint32_t l2 = kk ? Al[mt][0][1].y : Al[mt][0][1].x;
                    uint32_t l3 = kk ? Al[mt][1][1].y : Al[mt][1][1].x;
                    mma_bf16(acc[mt][nt], a0, a1, a2, a3, b0, b1);
                    mma_bf16(acc[mt][nt], l0, l1, l2, l3, b0, b1);
                    mma_bf16(acc[mt][nt], a0, a1, a2, a3, c0, c1);
                }
            }
        }
    }
}

__global__ __launch_bounds__(512, 1) void k_admm(const float* __restrict__ gQ,
                                                 const float* __restrict__ gV,
                                                 float* __restrict__ gOut) {
    extern __shared__ char smem[];
    uint32_t* rhU = (uint32_t*)(smem + SM_RH);
    uint32_t* rlU = (uint32_t*)(smem + SM_RL);
    __nv_bfloat16* w1B = (__nv_bfloat16*)(smem + SM_W1);
    __nv_bfloat16* w2B = (__nv_bfloat16*)(smem + SM_W2);
    float* sP   = (float*)(smem + SM_P);
    float* sCnt = (float*)(smem + SM_CNT);

    const int t = threadIdx.x;
    const int lane = t & 31, w = t >> 5;
    const int g = w >> 2;                 // 4 groups of 4 warps
    const int wg2 = w & 3;                // column slice
    const int gid = lane >> 2, tig = lane & 3;
    const int m0 = g * 32, n0 = wg2 * 32;
    const int rA = m0 + gid;
    const int b = blockIdx.x >> 4, row0 = (blockIdx.x & 15) * 128;
    const float* Vb = gV + b * 16384;
    const float* Qb = gQ + (size_t)(b * NN + row0) * 128;
    const int qb = tig * 8 + wg2 * 2;     // store-perm base

    // ---- prologue: Q split -> rhs (k-packed); V split -> W tiles ----
    for (int idx = t; idx < 8192; idx += 512) {
        int row = idx >> 6, p = idx & 63;
        float2 q = *(const float2*)(Qb + row * 128 + 2 * p);
        uint32_t hi, lo;
        split2(q.x, q.y, hi, lo);
        int qq = qperm(p);
        rhU[row * SU + qq] = hi;
        rlU[row * SU + qq] = lo;
        float2 v = *(const float2*)(Vb + row * 128 + 2 * p);
        split2(v.x, v.y, hi, lo);
        *(uint32_t*)(w1B + row * S136 + 2 * p) = hi;
        *(uint32_t*)(w2B + row * S136 + 2 * p) = lo;
    }
    __syncthreads();

    // ---- P = -(2/m) Q V^T + lambda/m -> sP; initial rhs = -P ----
    {
        float acc[2][4][4];
#pragma unroll
        for (int mt = 0; mt < 2; mt++)
#pragma unroll
            for (int nt = 0; nt < 4; nt++)
#pragma unroll
                for (int j = 0; j < 4; j++) acc[mt][nt][j] = 0.0f;
        gemm3(acc, rhU, rlU, w1B, w2B, rA, n0, tig, gid);
        __syncthreads();   // all reads of Q-rhs + V tiles done
        const float cP = -2.0f / 128.0f, cL = 0.1f / 128.0f;
#pragma unroll
        for (int mt = 0; mt < 2; mt++) {
            int ra = rA + 16 * mt, rb = ra + 8;
#pragma unroll
            for (int nt = 0; nt < 4; nt++) {
                int c = n0 + nt * 8 + 2 * tig;
                float4 pv;
                pv.x = cP * acc[mt][nt][0] + cL;
                pv.y = cP * acc[mt][nt][1] + cL;
                pv.z = cP * acc[mt][nt][2] + cL;
                pv.w = cP * acc[mt][nt][3] + cL;
                *(float2*)(sP + ra * 132 + c) = make_float2(pv.x, pv.y);
                *(float2*)(sP + rb * 132 + c) = make_float2(pv.z, pv.w);
                int qq = qb + (nt & 1) * 32 + (nt >> 1);
                uint32_t hi, lo;
                split2((0.0f - 0.0f) - pv.x, (0.0f - 0.0f) - pv.y, hi, lo);
                rhU[ra * SU + qq] = hi;
                rlU[ra * SU + qq] = lo;
                split2((0.0f - 0.0f) - pv.z, (0.0f - 0.0f) - pv.w, hi, lo);
                rhU[rb * SU + qq] = hi;
                rlU[rb * SU + qq] = lo;
            }
        }
    }
    // ---- load W bf16 hi/lo ----
    {
        const uint32_t* w1g = (const uint32_t*)gW1 + b * 8192;
        const uint32_t* w2g = (const uint32_t*)gW2 + b * 8192;
        for (int idx = t; idx < 8192; idx += 512) {
            int row = idx >> 6, cw = idx & 63;
            *(uint32_t*)(w1B + row * S136 + cw * 2) = w1g[row * 64 + cw];
            *(uint32_t*)(w2B + row * S136 + cw * 2) = w2g[row * 64 + cw];
        }
    }

    float xu[32];
#pragma unroll
    for (int e = 0; e < 32; e++) xu[e] = 0.0f;
    __syncthreads();   // W + initial rhs + sP visible

    // ---- 50 ADMM iterations: GEMM -> bar -> pointwise+store -> bar ----
    for (int it = 0; it < ITERS; it++) {
        float acc[2][4][4];
#pragma unroll
        for (int mt = 0; mt < 2; mt++)
#pragma unroll
            for (int nt = 0; nt < 4; nt++)
#pragma unroll
                for (int j = 0; j < 4; j++) acc[mt][nt][j] = 0.0f;
        gemm3(acc, rhU, rlU, w1B, w2B, rA, n0, tig, gid);
        barg128(1 + g);   // group's rhs reads done

#pragma unroll
        for (int mt = 0; mt < 2; mt++) {
            int ra = rA + 16 * mt, rb = ra + 8;
#pragma unroll
            for (int nt = 0; nt < 4; nt++) {
                int e = mt * 16 + nt * 4;
                int c = n0 + nt * 8 + 2 * tig;
                float2 p0 = *(float2*)(sP + ra * 132 + c);
                float2 p1 = *(float2*)(sP + rb * 132 + c);
                float pv[4] = {p0.x, p0.y, p1.x, p1.y};
                float r4[4];
#pragma unroll
                for (int j = 0; j < 4; j++) {
                    int ee = e + j;
                    float zd = fminf(fmaxf(xu[ee], 0.0f), 1.0f);
                    float ud = xu[ee] - zd;
                    float rhs = (zd - ud) - pv[j];
                    float x = rhs + acc[mt][nt][j];
                    xu[ee] = x + ud;
                    float zd2 = fminf(fmaxf(xu[ee], 0.0f), 1.0f);
                    float ud2 = xu[ee] - zd2;
                    r4[j] = (zd2 - ud2) - pv[j];
                }
                int qq = qb + (nt & 1) * 32 + (nt >> 1);
                uint32_t hi, lo;
                split2(r4[0], r4[1], hi, lo);
                rhU[ra * SU + qq] = hi;
                rlU[ra * SU + qq] = lo;
                split2(r4[2], r4[3], hi, lo);
                rhU[rb * SU + qq] = hi;
                rlU[rb * SU + qq] = lo;
            }
        }
        barg128(1 + g);   // new rhs visible
    }

    // ---- epilogue: counts, coeffs, out = coeff * (V/128) ----
    float z[32];
#pragma unroll
    for (int e = 0; e < 32; e++) z[e] = fminf(fmaxf(xu[e], 0.0f), 1.0f);
#pragma unroll
    for (int mt = 0; mt < 2; mt++) {
        int ra = rA + 16 * mt, rb = ra + 8;
        float c0s = 0.0f, c1s = 0.0f;
#pragma unroll
        for (int nt = 0; nt < 4; nt++) {
            int e = mt * 16 + nt * 4;
            c0s += ((z[e]     > 0.5f) ? 1.0f : 0.0f) + ((z[e + 1] > 0.5f) ? 1.0f : 0.0f);
            c1s += ((z[e + 2] > 0.5f) ? 1.0f : 0.0f) + ((z[e + 3] > 0.5f) ? 1.0f : 0.0f);
        }
        sCnt[ra * 16 + wg2 * 4 + tig] = c0s;
        sCnt[rb * 16 + wg2 * 4 + tig] = c1s;
    }
    barg128(1 + g);
    float inv[2][2];
#pragma unroll
    for (int mt = 0; mt < 2; mt++) {
        int ra = rA + 16 * mt, rb = ra + 8;
        float s0 = 0.0f, s1 = 0.0f;
#pragma unroll
        for (int k = 0; k < 16; k++) { s0 += sCnt[ra * 16 + k]; s1 += sCnt[rb * 16 + k]; }
        inv[mt][0] = 1.0f / (128.0f * (s0 + 1e-10f));
        inv[mt][1] = 1.0f / (128.0f * (s1 + 1e-10f));
    }
#pragma unroll
    for (int mt = 0; mt < 2; mt++) {
        int ra = rA + 16 * mt, rb = ra + 8;
#pragma unroll
        for (int nt = 0; nt < 4; nt++) {
            int e = mt * 16 + nt * 4;
            int qq = qb + (nt & 1) * 32 + (nt >> 1);
            uint32_t hi, lo;
            split2((z[e]     > 0.5f) ? inv[mt][0] : 0.0f,
                   (z[e + 1] > 0.5f) ? inv[mt][0] : 0.0f, hi, lo);
            rhU[ra * SU + qq] = hi;
            rlU[ra * SU + qq] = lo;
            split2((z[e + 2] > 0.5f) ? inv[mt][1] : 0.0f,
                   (z[e + 3] > 0.5f) ? inv[mt][1] : 0.0f, hi, lo);
            rhU[rb * SU + qq] = hi;
            rlU[rb * SU + qq] = lo;
        }
    }
    __syncthreads();   // all groups done iterating; W reads + coeff writes done
    // Vt split into W tiles: tile[d][m] = V[m][d]
    for (int idx = t; idx < 16384; idx += 512) {
        int m = idx >> 7, d = idx & 127;
        float f = Vb[idx];
        __nv_bfloat16 h = __float2bfloat16(f);
        w1B[d * S136 + m] = h;
        w2B[d * S136 + m] = __float2bfloat16(f - __bfloat162float(h));
    }
    __syncthreads();

    {
        float acc[2][4][4];
#pragma unroll
        for (int mt = 0; mt < 2; mt++)
#pragma unroll
            for (int nt = 0; nt < 4; nt++)
#pragma unroll
                for (int j = 0; j < 4; j++) acc[mt][nt][j] = 0.0f;
        gemm3(acc, rhU, rlU, w1B, w2B, rA, n0, tig, gid);
        float* ob = gOut + (size_t)(b * NN + row0) * 128;
#pragma unroll
        for (int mt = 0; mt < 2; mt++) {
            int ra = rA + 16 * mt, rb = ra + 8;
#pragma unroll
            for (int nt = 0; nt < 4; nt++) {
                int c = n0 + nt * 8 + 2 * tig;
                *(float2*)(ob + ra * 128 + c) = make_float2(acc[mt][nt][0], acc[mt][nt][1]);
                *(float2*)(ob + rb * 128 + c) = make_float2(acc[mt][nt][2], acc[mt][nt][3]);
            }
        }
    }
}

// ============================================================================

extern "C" void kernel_launch(void* const* d_in, const int* in_sizes, int n_in,
                              void* d_out, int out_size) {
    const float* gQ = (const float*)d_in[0];
    const float* gV = (const float*)d_in[1];
    if (n_in >= 2 && in_sizes[0] == BB * 128 * 128 && in_sizes[1] == BB * NN * 128) {
        gV = (const float*)d_in[0];
        gQ = (const float*)d_in[1];
    }
    float* out = (float*)d_out;

    const int SMEM_E   = 128 * 132 * 4;                // 67584
    const int SMEM_MM1 = (8 * 129 + 128 * 128) * 4;    // 69664
    const int SMEM_MM2 = (16 * 129 + 128 * 128) * 4;   // 73792

    cudaFuncSetAttribute(kE,   cudaFuncAttributeMaxDynamicSharedMemorySize, SMEM_E);
    cudaFuncSetAttribute(kMM1, cudaFuncAttributeMaxDynamicSharedMemorySize, SMEM_MM1);
    cudaFuncSetAttribute(kMM2, cudaFuncAttributeMaxDynamicSharedMemorySize, SMEM_MM2);
    cudaFuncSetAttribute(k_admm, cudaFuncAttributeMaxDynamicSharedMemorySize, SMEM_ADMM);

    kE<<<64, 256, SMEM_E>>>(gV);
    kMM1<<<128, 256, SMEM_MM1>>>();       // E2 = E*E ; S = I - E + E2
    kMM2<<<128, 256, SMEM_MM2>>>();       // W = E2*S - E -> bf16 hi/lo
    k_admm<<<BB * (NN / 128), 512, SMEM_ADMM>>>(gQ, gV, out);
}

// round 16
// speedup vs baseline: 1.2987x; 1.2987x over previous
#include <cuda_runtime.h>
#include <cuda_bf16.h>
#include <cstdint>

#define BB 8
#define NN 2048
#define ITERS 50

// ---- device scratch (no allocs allowed) ----
__device__ float gE[BB * 16384], gE2[BB * 16384], gS[BB * 16384];
__device__ __nv_bfloat16 gW1[BB * 16384], gW2[BB * 16384];

// ---- f32x2 helpers (prep kernels) ----
__device__ __forceinline__ unsigned long long ffma2(unsigned long long a,
                                                    unsigned long long b,
                                                    unsigned long long c) {
    unsigned long long d;
    asm("fma.rn.f32x2 %0, %1, %2, %3;" : "=l"(d) : "l"(a), "l"(b), "l"(c));
    return d;
}
__device__ __forceinline__ unsigned long long pack2(float x) {
    union { unsigned long long u; float2 f; } c; c.f = make_float2(x, x); return c.u;
}
__device__ __forceinline__ float2 unpack2(unsigned long long v) {
    union { unsigned long long u; float2 f; } c; c.u = v; return c.f;
}

// ---- HMMA m16n8k16 bf16 -> f32 ----
__device__ __forceinline__ void mma_bf16(float c[4],
                                         uint32_t a0, uint32_t a1, uint32_t a2, uint32_t a3,
                                         uint32_t b0, uint32_t b1) {
    asm volatile(
        "mma.sync.aligned.m16n8k16.row.col.f32.bf16.bf16.f32 "
        "{%0,%1,%2,%3}, {%4,%5,%6,%7}, {%8,%9}, {%0,%1,%2,%3};"
        : "+f"(c[0]), "+f"(c[1]), "+f"(c[2]), "+f"(c[3])
        : "r"(a0), "r"(a1), "r"(a2), "r"(a3), "r"(b0), "r"(b1));
}

__device__ __forceinline__ void split2(float x, float y, uint32_t& hi, uint32_t& lo) {
    __nv_bfloat162 h = __float22bfloat162_rn(make_float2(x, y));
    float2 hb = __bfloat1622float2(h);
    __nv_bfloat162 l = __float22bfloat162_rn(make_float2(x - hb.x, y - hb.y));
    hi = *(uint32_t*)&h;
    lo = *(uint32_t*)&l;
}

__device__ __forceinline__ void barg128(int id) {
    asm volatile("bar.sync %0, %1;" :: "r"(id), "r"(128) : "memory");
}

// ============================================================================
// kE: E = (1/8192) V V^T.  grid 128 (b*16 + 8-row slice) x 256 thr.
// Per thread: row r, 4 cols (2 ffma2 accs). Same even/odd pairing + d-order
// as before -> E bit-identical per element.
// ============================================================================
__global__ __launch_bounds__(256, 1) void kE(const float* __restrict__ gV) {
    extern __shared__ float sm[];
    float* sVt = sm;                         // [128][132]
    const int b = blockIdx.x >> 4, r0 = (blockIdx.x & 15) * 8;
    const int t = threadIdx.x;
    for (int idx = t; idx < 16384; idx += 256) {
        int m = idx >> 7, d = idx & 127;
        sVt[d * 132 + m] = gV[b * 16384 + idx];
    }
    __syncthreads();
    const int r = r0 + (t & 7), i0 = (t >> 3) * 4;
    unsigned long long acc[2];
    acc[0] = 0ULL; acc[1] = 0ULL;
#pragma unroll 8
    for (int d = 0; d < 128; d++) {
        unsigned long long a2 = pack2(sVt[d * 132 + r]);
        ulonglong2 mv = *(const ulonglong2*)(sVt + d * 132 + i0);
        acc[0] = ffma2(mv.x, a2, acc[0]);
        acc[1] = ffma2(mv.y, a2, acc[1]);
    }
    const float sc = 1.0f / 8192.0f;
#pragma unroll
    for (int e = 0; e < 2; e++) {
        float2 v = unpack2(acc[e]);
        gE[b * 16384 + r * 128 + i0 + 2 * e]     = sc * v.x;
        gE[b * 16384 + r * 128 + i0 + 2 * e + 1] = sc * v.y;
    }
}

// ============================================================================
// kMM1: E2 = E*E ; S = I - E + E2.   grid 128 x 256.
// ============================================================================
__global__ __launch_bounds__(256, 1) void kMM1() {
    extern __shared__ float sm[];
    float* sA = sm;                 // E slice [8][129]
    float* sB = sm + 8 * 129;       // E full [128][128]
    const int b = blockIdx.x >> 4, r0 = (blockIdx.x & 15) * 8;
    const int t = threadIdx.x;
    for (int idx = t; idx < 1024; idx += 256) {
        int row = idx >> 7, j = idx & 127;
        sA[row * 129 + j] = gE[b * 16384 + (r0 + row) * 128 + j];
    }
    for (int idx = t; idx < 4096; idx += 256)
        ((float4*)sB)[idx] = ((const float4*)(gE + b * 16384))[idx];
    __syncthreads();
    const int rl = t & 7, r = r0 + rl, i0 = (t >> 3) * 4;
    unsigned long long acc[2];
    acc[0] = 0ULL; acc[1] = 0ULL;
#pragma unroll 8
    for (int j = 0; j < 128; j++) {
        unsigned long long a2 = pack2(sA[rl * 129 + j]);
        ulonglong2 mv = *(const ulonglong2*)(sB + j * 128 + i0);
        acc[0] = ffma2(mv.x, a2, acc[0]);
        acc[1] = ffma2(mv.y, a2, acc[1]);
    }
#pragma unroll
    for (int e = 0; e < 2; e++) {
        float2 v = unpack2(acc[e]);
        int c0 = i0 + 2 * e;
        gE2[b * 16384 + r * 128 + c0]     = v.x;
        gE2[b * 16384 + r * 128 + c0 + 1] = v.y;
        gS[b * 16384 + r * 128 + c0]     = ((r == c0)     ? 1.0f : 0.0f) - sA[rl * 129 + c0]     + v.x;
        gS[b * 16384 + r * 128 + c0 + 1] = ((r == c0 + 1) ? 1.0f : 0.0f) - sA[rl * 129 + c0 + 1] + v.y;
    }
}

// ============================================================================
// kMM2: W = E2*S - E  (deg-4 Neumann; trunc ~1e-6) -> bf16 hi/lo.  grid 128 x 256.
// ============================================================================
__global__ __launch_bounds__(256, 1) void kMM2() {
    extern __shared__ float sm[];
    float* sA = sm;                 // E2 slice [8][129]
    float* sE = sm + 8 * 129;       // E slice  [8][129]
    float* sB = sm + 16 * 129;      // S full [128][128]
    const int b = blockIdx.x >> 4, r0 = (blockIdx.x & 15) * 8;
    const int t = threadIdx.x;
    for (int idx = t; idx < 1024; idx += 256) {
        int row = idx >> 7, j = idx & 127;
        sA[row * 129 + j] = gE2[b * 16384 + (r0 + row) * 128 + j];
        sE[row * 129 + j] = gE [b * 16384 + (r0 + row) * 128 + j];
    }
    for (int idx = t; idx < 4096; idx += 256)
        ((float4*)sB)[idx] = ((const float4*)(gS + b * 16384))[idx];
    __syncthreads();
    const int rl = t & 7, r = r0 + rl, k0 = (t >> 3) * 4;
    unsigned long long acc[2];
    acc[0] = 0ULL; acc[1] = 0ULL;
#pragma unroll 8
    for (int j = 0; j < 128; j++) {
        unsigned long long a2 = pack2(sA[rl * 129 + j]);
        ulonglong2 mv = *(const ulonglong2*)(sB + j * 128 + k0);
        acc[0] = ffma2(mv.x, a2, acc[0]);
        acc[1] = ffma2(mv.y, a2, acc[1]);
    }
    uint32_t* o1 = (uint32_t*)gW1 + b * 8192;
    uint32_t* o2 = (uint32_t*)gW2 + b * 8192;
#pragma unroll
    for (int e = 0; e < 2; e++) {
        float2 tv = unpack2(acc[e]);
        int k = k0 + 2 * e;
        float wx = tv.x - sE[rl * 129 + k];
        float wy = tv.y - sE[rl * 129 + k + 1];
        uint32_t hi, lo;
        split2(wx, wy, hi, lo);
        o1[r * 64 + (k >> 1)] = hi;
        o2[r * 64 + (k >> 1)] = lo;
    }
}

// ============================================================================
// k_admm (CHAMPION structure, benched 260.9us): fused P-prep + 50 HMMA ADMM
// iters + epilogue. 4 independent 128-thread groups (rows 32g..32g+31), named
// barriers; double-buffered rhs tiles -> ONE barrier/iter; P in registers;
// scalar LDS fragment loads on linear S136 layout. Arithmetic chain and MMA
// order bit-identical (k0 asc; Ah*W1, Al*W1, Ah*W2).
// New this round: vectorized prologue loads only (uint4/float4) — values same.
// ============================================================================
#define S136 136
#define SM_B0H 0                 // rhs buf0 hi [128][136] bf16
#define SM_B0L 34816
#define SM_B1H 69632             // rhs buf1 hi/lo
#define SM_B1L 104448
#define SM_W1  139264            // W hi (V hi in prologue / Vt hi in epilogue)
#define SM_W2  174080
#define SM_CNT 208896            // f32 [128][16] = 8192 B
#define SMEM_ADMM 217088

__device__ __forceinline__ void gemm3s(float acc[2][4][4],
                                       const __nv_bfloat16* __restrict__ rhB,
                                       const __nv_bfloat16* __restrict__ rlB,
                                       const __nv_bfloat16* __restrict__ w1B,
                                       const __nv_bfloat16* __restrict__ w2B,
                                       int rA, int n0, int tig, int gid) {
#pragma unroll
    for (int k0 = 0; k0 < 8; k0++) {
        int ka = k0 * 16 + 2 * tig;
        uint32_t ah[2][4], al[2][4];
#pragma unroll
        for (int mt = 0; mt < 2; mt++) {
            int ra = rA + 16 * mt, rb = ra + 8;
            ah[mt][0] = *(const uint32_t*)(rhB + ra * S136 + ka);
            ah[mt][1] = *(const uint32_t*)(rhB + rb * S136 + ka);
            ah[mt][2] = *(const uint32_t*)(rhB + ra * S136 + ka + 8);
            ah[mt][3] = *(const uint32_t*)(rhB + rb * S136 + ka + 8);
            al[mt][0] = *(const uint32_t*)(rlB + ra * S136 + ka);
            al[mt][1] = *(const uint32_t*)(rlB + rb * S136 + ka);
            al[mt][2] = *(const uint32_t*)(rlB + ra * S136 + ka + 8);
            al[mt][3] = *(const uint32_t*)(rlB + rb * S136 + ka + 8);
        }
#pragma unroll
        for (int nt = 0; nt < 4; nt++) {
            int bn = n0 + nt * 8 + gid;
            uint32_t b0 = *(const uint32_t*)(w1B + bn * S136 + ka);
            uint32_t b1 = *(const uint32_t*)(w1B + bn * S136 + ka + 8);
            uint32_t c0 = *(const uint32_t*)(w2B + bn * S136 + ka);
            uint32_t c1 = *(const uint32_t*)(w2B + bn * S136 + ka + 8);
#pragma unroll
            for (int mt = 0; mt < 2; mt++) {
                mma_bf16(acc[mt][nt], ah[mt][0], ah[mt][1], ah[mt][2], ah[mt][3], b0, b1);
                mma_bf16(acc[mt][nt], al[mt][0], al[mt][1], al[mt][2], al[mt][3], b0, b1);
                mma_bf16(acc[mt][nt], ah[mt][0], ah[mt][1], ah[mt][2], ah[mt][3], c0, c1);
            }
        }
    }
}

__global__ __launch_bounds__(512, 1) void k_admm(const float* __restrict__ gQ,
                                                 const float* __restrict__ gV,
                                                 float* __restrict__ gOut) {
    extern __shared__ char smem[];
    __nv_bfloat16* rh0 = (__nv_bfloat16*)(smem + SM_B0H);
    __nv_bfloat16* rl0 = (__nv_bfloat16*)(smem + SM_B0L);
    __nv_bfloat16* rh1 = (__nv_bfloat16*)(smem + SM_B1H);
    __nv_bfloat16* rl1 = (__nv_bfloat16*)(smem + SM_B1L);
    __nv_bfloat16* w1B = (__nv_bfloat16*)(smem + SM_W1);
    __nv_bfloat16* w2B = (__nv_bfloat16*)(smem + SM_W2);
    float* sCnt = (float*)(smem + SM_CNT);

    const int t = threadIdx.x;
    const int lane = t & 31, w = t >> 5;
    const int g = w >> 2;                 // 4 groups of 4 warps
    const int wg2 = w & 3;                // column slice within group
    const int gid = lane >> 2, tig = lane & 3;
    const int m0 = g * 32, n0 = wg2 * 32;
    const int rA = m0 + gid;
    const int b = blockIdx.x >> 4, row0 = (blockIdx.x & 15) * 128;
    const float* Vb = gV + b * 16384;
    const float* Qb = gQ + (size_t)(b * NN + row0) * 128;

    // ---- prologue: Q split -> buf0; V split -> W tiles (float4 loads) ----
    for (int idx = t; idx < 4096; idx += 512) {
        int row = idx >> 5, p4 = (idx & 31) * 4;      // 4 float cols
        float4 q = *(const float4*)(Qb + row * 128 + p4);
        uint32_t h0, l0, h1, l1;
        split2(q.x, q.y, h0, l0);
        split2(q.z, q.w, h1, l1);
        *(uint2*)(rh0 + row * S136 + p4) = make_uint2(h0, h1);
        *(uint2*)(rl0 + row * S136 + p4) = make_uint2(l0, l1);
        float4 v = *(const float4*)(Vb + row * 128 + p4);
        split2(v.x, v.y, h0, l0);
        split2(v.z, v.w, h1, l1);
        *(uint2*)(w1B + row * S136 + p4) = make_uint2(h0, h1);
        *(uint2*)(w2B + row * S136 + p4) = make_uint2(l0, l1);
    }
    __syncthreads();

    // ---- P = -(2/m) Q V^T + lambda/m -> registers ----
    float P[32];
    {
        float acc[2][4][4];
#pragma unroll
        for (int mt = 0; mt < 2; mt++)
#pragma unroll
            for (int nt = 0; nt < 4; nt++)
#pragma unroll
                for (int j = 0; j < 4; j++) acc[mt][nt][j] = 0.0f;
        gemm3s(acc, rh0, rl0, w1B, w2B, rA, n0, tig, gid);
        const float cP = -2.0f / 128.0f, cL = 0.1f / 128.0f;
#pragma unroll
        for (int mt = 0; mt < 2; mt++)
#pragma unroll
            for (int nt = 0; nt < 4; nt++)
#pragma unroll
                for (int j = 0; j < 4; j++)
                    P[mt * 16 + nt * 4 + j] = cP * acc[mt][nt][j] + cL;
    }
    __syncthreads();   // Q/V tile reads done

    // ---- load W bf16 hi/lo (uint4 vectorized) ----
    {
        const uint4* w1g = (const uint4*)((const uint32_t*)gW1 + b * 8192);
        const uint4* w2g = (const uint4*)((const uint32_t*)gW2 + b * 8192);
        for (int idx = t; idx < 2048; idx += 512) {
            int row = idx >> 4, cw4 = (idx & 15) * 4;   // words cw4..cw4+3
            uint4 v1 = w1g[idx];
            uint4 v2 = w2g[idx];
            *(uint4*)(w1B + row * S136 + cw4 * 2) = v1;
            *(uint4*)(w2B + row * S136 + cw4 * 2) = v2;
        }
    }

    float xu[32];
#pragma unroll
    for (int e = 0; e < 32; e++) xu[e] = 0.0f;

    // initial rhs (it=0): z=u=0 -> (0-0)-P, into buf0
#pragma unroll
    for (int mt = 0; mt < 2; mt++) {
        int ra = rA + 16 * mt, rb = ra + 8;
#pragma unroll
        for (int nt = 0; nt < 4; nt++) {
            int e = mt * 16 + nt * 4;
            int c = n0 + nt * 8 + 2 * tig;
            uint32_t hi, lo;
            split2((0.0f - 0.0f) - P[e], (0.0f - 0.0f) - P[e + 1], hi, lo);
            *(uint32_t*)(rh0 + ra * S136 + c) = hi;
            *(uint32_t*)(rl0 + ra * S136 + c) = lo;
            split2((0.0f - 0.0f) - P[e + 2], (0.0f - 0.0f) - P[e + 3], hi, lo);
            *(uint32_t*)(rh0 + rb * S136 + c) = hi;
            *(uint32_t*)(rl0 + rb * S136 + c) = lo;
        }
    }
    __syncthreads();   // covers W load + initial rhs

    // ---- 50 ADMM iterations: GEMM(buf p) -> fused pointwise+store(buf 1-p) -> bar ----
    for (int it = 0; it < ITERS; it++) {
        const __nv_bfloat16* rhR = (it & 1) ? rh1 : rh0;
        const __nv_bfloat16* rlR = (it & 1) ? rl1 : rl0;
        __nv_bfloat16* rhW = (it & 1) ? rh0 : rh1;
        __nv_bfloat16* rlW = (it & 1) ? rl0 : rl1;

        float acc[2][4][4];
#pragma unroll
        for (int mt = 0; mt < 2; mt++)
#pragma unroll
            for (int nt = 0; nt < 4; nt++)
#pragma unroll
                for (int j = 0; j < 4; j++) acc[mt][nt][j] = 0.0f;
        gemm3s(acc, rhR, rlR, w1B, w2B, rA, n0, tig, gid);

#pragma unroll
        for (int mt = 0; mt < 2; mt++) {
            int ra = rA + 16 * mt, rb = ra + 8;
#pragma unroll
            for (int nt = 0; nt < 4; nt++) {
                int e = mt * 16 + nt * 4;
                int c = n0 + nt * 8 + 2 * tig;
                float r4[4];
#pragma unroll
                for (int j = 0; j < 4; j++) {
                    int ee = e + j;
                    float zd = fminf(fmaxf(xu[ee], 0.0f), 1.0f);
                    float ud = xu[ee] - zd;
                    float rhs = (zd - ud) - P[ee];
                    float x = rhs + acc[mt][nt][j];
                    xu[ee] = x + ud;
                    float zd2 = fminf(fmaxf(xu[ee], 0.0f), 1.0f);
                    float ud2 = xu[ee] - zd2;
                    r4[j] = (zd2 - ud2) - P[ee];
                }
                uint32_t hi, lo;
                split2(r4[0], r4[1], hi, lo);
                *(uint32_t*)(rhW + ra * S136 + c) = hi;
                *(uint32_t*)(rlW + ra * S136 + c) = lo;
                split2(r4[2], r4[3], hi, lo);
                *(uint32_t*)(rhW + rb * S136 + c) = hi;
                *(uint32_t*)(rlW + rb * S136 + c) = lo;
            }
        }
        barg128(1 + g);
    }

    // ---- epilogue: counts, coeffs, out = coeff * (V/128) ----
    float z[32];
#pragma unroll
    for (int e = 0; e < 32; e++) z[e] = fminf(fmaxf(xu[e], 0.0f), 1.0f);
#pragma unroll
    for (int mt = 0; mt < 2; mt++) {
        int ra = rA + 16 * mt, rb = ra + 8;
        float c0s = 0.0f, c1s = 0.0f;
#pragma unroll
        for (int nt = 0; nt < 4; nt++) {
            int e = mt * 16 + nt * 4;
            c0s += ((z[e]     > 0.5f) ? 1.0f : 0.0f) + ((z[e + 1] > 0.5f) ? 1.0f : 0.0f);
            c1s += ((z[e + 2] > 0.5f) ? 1.0f : 0.0f) + ((z[e + 3] > 0.5f) ? 1.0f : 0.0f);
        }
        sCnt[ra * 16 + wg2 * 4 + tig] = c0s;
        sCnt[rb * 16 + wg2 * 4 + tig] = c1s;
    }
    barg128(1 + g);
    float inv[2][2];
#pragma unroll
    for (int mt = 0; mt < 2; mt++) {
        int ra = rA + 16 * mt, rb = ra + 8;
        float s0 = 0.0f, s1 = 0.0f;
#pragma unroll
        for (int k = 0; k < 16; k++) { s0 += sCnt[ra * 16 + k]; s1 += sCnt[rb * 16 + k]; }
        inv[mt][0] = 1.0f / (128.0f * (s0 + 1e-10f));
        inv[mt][1] = 1.0f / (128.0f * (s1 + 1e-10f));
    }
#pragma unroll
    for (int mt = 0; mt < 2; mt++) {
        int ra = rA + 16 * mt, rb = ra + 8;
#pragma unroll
        for (int nt = 0; nt < 4; nt++) {
            int e = mt * 16 + nt * 4;
            int c = n0 + nt * 8 + 2 * tig;
            uint32_t hi, lo;
            split2((z[e]     > 0.5f) ? inv[mt][0] : 0.0f,
                   (z[e + 1] > 0.5f) ? inv[mt][0] : 0.0f, hi, lo);
            *(uint32_t*)(rh0 + ra * S136 + c) = hi;
            *(uint32_t*)(rl0 + ra * S136 + c) = lo;
            split2((z[e + 2] > 0.5f) ? inv[mt][1] : 0.0f,
                   (z[e + 3] > 0.5f) ? inv[mt][1] : 0.0f, hi, lo);
            *(uint32_t*)(rh0 + rb * S136 + c) = hi;
            *(uint32_t*)(rl0 + rb * S136 + c) = lo;
        }
    }
    __syncthreads();   // all groups done with W tiles + coeff writes
    for (int idx = t; idx < 16384; idx += 512) {
        int m = idx >> 7, d = idx & 127;
        float f = Vb[idx];
        __nv_bfloat16 h = __float2bfloat16(f);
        w1B[d * S136 + m] = h;
        w2B[d * S136 + m] = __float2bfloat16(f - __bfloat162float(h));
    }
    __syncthreads();

    {
        float acc[2][4][4];
#pragma unroll
        for (int mt = 0; mt < 2; mt++)
#pragma unroll
            for (int nt = 0; nt < 4; nt++)
#pragma unroll
                for (int j = 0; j < 4; j++) acc[mt][nt][j] = 0.0f;
        gemm3s(acc, rh0, rl0, w1B, w2B, rA, n0, tig, gid);
        float* ob = gOut + (size_t)(b * NN + row0) * 128;
#pragma unroll
        for (int mt = 0; mt < 2; mt++) {
            int ra = rA + 16 * mt, rb = ra + 8;
#pragma unroll
            for (int nt = 0; nt < 4; nt++) {
                int c = n0 + nt * 8 + 2 * tig;
                *(float2*)(ob + ra * 128 + c) = make_float2(acc[mt][nt][0], acc[mt][nt][1]);
                *(float2*)(ob + rb * 128 + c) = make_float2(acc[mt][nt][2], acc[mt][nt][3]);
            }
        }
    }
}

// ============================================================================

extern "C" void kernel_launch(void* const* d_in, const int* in_sizes, int n_in,
                              void* d_out, int out_size) {
    const float* gQ = (const float*)d_in[0];
    const float* gV = (const float*)d_in[1];
    if (n_in >= 2 && in_sizes[0] == BB * 128 * 128 && in_sizes[1] == BB * NN * 128) {
        gV = (const float*)d_in[0];
        gQ = (const float*)d_in[1];
    }
    float* out = (float*)d_out;

    const int SMEM_E   = 128 * 132 * 4;                // 67584
    const int SMEM_MM1 = (8 * 129 + 128 * 128) * 4;    // 69664
    const int SMEM_MM2 = (16 * 129 + 128 * 128) * 4;   // 73792

    cudaFuncSetAttribute(kE,   cudaFuncAttributeMaxDynamicSharedMemorySize, SMEM_E);
    cudaFuncSetAttribute(kMM1, cudaFuncAttributeMaxDynamicSharedMemorySize, SMEM_MM1);
    cudaFuncSetAttribute(kMM2, cudaFuncAttributeMaxDynamicSharedMemorySize, SMEM_MM2);
    cudaFuncSetAttribute(k_admm, cudaFuncAttributeMaxDynamicSharedMemorySize, SMEM_ADMM);

    kE<<<128, 256, SMEM_E>>>(gV);
    kMM1<<<128, 256, SMEM_MM1>>>();       // E2 = E*E ; S = I - E + E2
    kMM2<<<128, 256, SMEM_MM2>>>();       // W = E2*S - E -> bf16 hi/lo
    k_admm<<<BB * (NN / 128), 512, SMEM_ADMM>>>(gQ, gV, out);
}

// round 17
// speedup vs baseline: 1.3189x; 1.0155x over previous
#include <cuda_runtime.h>
#include <cuda_bf16.h>
#include <cstdint>

#define BB 8
#define NN 2048
#define ITERS 50

// ---- device scratch (no allocs allowed) ----
__device__ float gE[BB * 16384], gE2[BB * 16384], gS[BB * 16384];
__device__ __nv_bfloat16 gW1[BB * 16384], gW2[BB * 16384];

// ---- f32x2 helpers (prep kernels) ----
__device__ __forceinline__ unsigned long long ffma2(unsigned long long a,
                                                    unsigned long long b,
                                                    unsigned long long c) {
    unsigned long long d;
    asm("fma.rn.f32x2 %0, %1, %2, %3;" : "=l"(d) : "l"(a), "l"(b), "l"(c));
    return d;
}
__device__ __forceinline__ unsigned long long pack2(float x) {
    union { unsigned long long u; float2 f; } c; c.f = make_float2(x, x); return c.u;
}
__device__ __forceinline__ float2 unpack2(unsigned long long v) {
    union { unsigned long long u; float2 f; } c; c.u = v; return c.f;
}

// ---- HMMA m16n8k16 bf16 -> f32 ----
__device__ __forceinline__ void mma_bf16(float c[4],
                                         uint32_t a0, uint32_t a1, uint32_t a2, uint32_t a3,
                                         uint32_t b0, uint32_t b1) {
    asm volatile(
        "mma.sync.aligned.m16n8k16.row.col.f32.bf16.bf16.f32 "
        "{%0,%1,%2,%3}, {%4,%5,%6,%7}, {%8,%9}, {%0,%1,%2,%3};"
        : "+f"(c[0]), "+f"(c[1]), "+f"(c[2]), "+f"(c[3])
        : "r"(a0), "r"(a1), "r"(a2), "r"(a3), "r"(b0), "r"(b1));
}

__device__ __forceinline__ void split2(float x, float y, uint32_t& hi, uint32_t& lo) {
    __nv_bfloat162 h = __float22bfloat162_rn(make_float2(x, y));
    float2 hb = __bfloat1622float2(h);
    __nv_bfloat162 l = __float22bfloat162_rn(make_float2(x - hb.x, y - hb.y));
    hi = *(uint32_t*)&h;
    lo = *(uint32_t*)&l;
}

__device__ __forceinline__ void barg128(int id) {
    asm volatile("bar.sync %0, %1;" :: "r"(id), "r"(128) : "memory");
}

// ============================================================================
// kE: E = (1/8192) V V^T.  grid 128 (b*16 + 8-row slice) x 256 thr.
// ============================================================================
__global__ __launch_bounds__(256, 1) void kE(const float* __restrict__ gV) {
    extern __shared__ float sm[];
    float* sVt = sm;                         // [128][132]
    const int b = blockIdx.x >> 4, r0 = (blockIdx.x & 15) * 8;
    const int t = threadIdx.x;
    for (int idx = t; idx < 16384; idx += 256) {
        int m = idx >> 7, d = idx & 127;
        sVt[d * 132 + m] = gV[b * 16384 + idx];
    }
    __syncthreads();
    const int r = r0 + (t & 7), i0 = (t >> 3) * 4;
    unsigned long long acc[2];
    acc[0] = 0ULL; acc[1] = 0ULL;
#pragma unroll 8
    for (int d = 0; d < 128; d++) {
        unsigned long long a2 = pack2(sVt[d * 132 + r]);
        ulonglong2 mv = *(const ulonglong2*)(sVt + d * 132 + i0);
        acc[0] = ffma2(mv.x, a2, acc[0]);
        acc[1] = ffma2(mv.y, a2, acc[1]);
    }
    const float sc = 1.0f / 8192.0f;
#pragma unroll
    for (int e = 0; e < 2; e++) {
        float2 v = unpack2(acc[e]);
        gE[b * 16384 + r * 128 + i0 + 2 * e]     = sc * v.x;
        gE[b * 16384 + r * 128 + i0 + 2 * e + 1] = sc * v.y;
    }
}

// ============================================================================
// kMM1: E2 = E*E ; S = I - E + E2.   grid 128 x 256.
// ============================================================================
__global__ __launch_bounds__(256, 1) void kMM1() {
    extern __shared__ float sm[];
    float* sA = sm;                 // E slice [8][129]
    float* sB = sm + 8 * 129;       // E full [128][128]
    const int b = blockIdx.x >> 4, r0 = (blockIdx.x & 15) * 8;
    const int t = threadIdx.x;
    for (int idx = t; idx < 1024; idx += 256) {
        int row = idx >> 7, j = idx & 127;
        sA[row * 129 + j] = gE[b * 16384 + (r0 + row) * 128 + j];
    }
    for (int idx = t; idx < 4096; idx += 256)
        ((float4*)sB)[idx] = ((const float4*)(gE + b * 16384))[idx];
    __syncthreads();
    const int rl = t & 7, r = r0 + rl, i0 = (t >> 3) * 4;
    unsigned long long acc[2];
    acc[0] = 0ULL; acc[1] = 0ULL;
#pragma unroll 8
    for (int j = 0; j < 128; j++) {
        unsigned long long a2 = pack2(sA[rl * 129 + j]);
        ulonglong2 mv = *(const ulonglong2*)(sB + j * 128 + i0);
        acc[0] = ffma2(mv.x, a2, acc[0]);
        acc[1] = ffma2(mv.y, a2, acc[1]);
    }
#pragma unroll
    for (int e = 0; e < 2; e++) {
        float2 v = unpack2(acc[e]);
        int c0 = i0 + 2 * e;
        gE2[b * 16384 + r * 128 + c0]     = v.x;
        gE2[b * 16384 + r * 128 + c0 + 1] = v.y;
        gS[b * 16384 + r * 128 + c0]     = ((r == c0)     ? 1.0f : 0.0f) - sA[rl * 129 + c0]     + v.x;
        gS[b * 16384 + r * 128 + c0 + 1] = ((r == c0 + 1) ? 1.0f : 0.0f) - sA[rl * 129 + c0 + 1] + v.y;
    }
}

// ============================================================================
// kMM2: W = E2*S - E  (deg-4 Neumann; trunc ~1e-6) -> bf16 hi/lo.  grid 128 x 256.
// ============================================================================
__global__ __launch_bounds__(256, 1) void kMM2() {
    extern __shared__ float sm[];
    float* sA = sm;                 // E2 slice [8][129]
    float* sE = sm + 8 * 129;       // E slice  [8][129]
    float* sB = sm + 16 * 129;      // S full [128][128]
    const int b = blockIdx.x >> 4, r0 = (blockIdx.x & 15) * 8;
    const int t = threadIdx.x;
    for (int idx = t; idx < 1024; idx += 256) {
        int row = idx >> 7, j = idx & 127;
        sA[row * 129 + j] = gE2[b * 16384 + (r0 + row) * 128 + j];
        sE[row * 129 + j] = gE [b * 16384 + (r0 + row) * 128 + j];
    }
    for (int idx = t; idx < 4096; idx += 256)
        ((float4*)sB)[idx] = ((const float4*)(gS + b * 16384))[idx];
    __syncthreads();
    const int rl = t & 7, r = r0 + rl, k0 = (t >> 3) * 4;
    unsigned long long acc[2];
    acc[0] = 0ULL; acc[1] = 0ULL;
#pragma unroll 8
    for (int j = 0; j < 128; j++) {
        unsigned long long a2 = pack2(sA[rl * 129 + j]);
        ulonglong2 mv = *(const ulonglong2*)(sB + j * 128 + k0);
        acc[0] = ffma2(mv.x, a2, acc[0]);
        acc[1] = ffma2(mv.y, a2, acc[1]);
    }
    uint32_t* o1 = (uint32_t*)gW1 + b * 8192;
    uint32_t* o2 = (uint32_t*)gW2 + b * 8192;
#pragma unroll
    for (int e = 0; e < 2; e++) {
        float2 tv = unpack2(acc[e]);
        int k = k0 + 2 * e;
        float wx = tv.x - sE[rl * 129 + k];
        float wy = tv.y - sE[rl * 129 + k + 1];
        uint32_t hi, lo;
        split2(wx, wy, hi, lo);
        o1[r * 64 + (k >> 1)] = hi;
        o2[r * 64 + (k >> 1)] = lo;
    }
}

// ============================================================================
// k_admm (champion structure + MMA term-major reorder + dead last store skip).
// 4 independent 128-thread groups, double-buffered rhs, 1 barrier/iter, P in
// regs, scalar LDS on linear S136. Per-acc MMA order unchanged (term1->2->3)
// -> bit-identical; only cross-acc issue interleaving differs.
// ============================================================================
#define S136 136
#define SM_B0H 0                 // rhs buf0 hi [128][136] bf16
#define SM_B0L 34816
#define SM_B1H 69632             // rhs buf1 hi/lo
#define SM_B1L 104448
#define SM_W1  139264            // W hi (V hi in prologue / Vt hi in epilogue)
#define SM_W2  174080
#define SM_CNT 208896            // f32 [128][16] = 8192 B
#define SMEM_ADMM 217088

__device__ __forceinline__ void gemm3s(float acc[2][4][4],
                                       const __nv_bfloat16* __restrict__ rhB,
                                       const __nv_bfloat16* __restrict__ rlB,
                                       const __nv_bfloat16* __restrict__ w1B,
                                       const __nv_bfloat16* __restrict__ w2B,
                                       int rA, int n0, int tig, int gid) {
#pragma unroll
    for (int k0 = 0; k0 < 8; k0++) {
        int ka = k0 * 16 + 2 * tig;
        uint32_t ah[2][4], al[2][4];
#pragma unroll
        for (int mt = 0; mt < 2; mt++) {
            int ra = rA + 16 * mt, rb = ra + 8;
            ah[mt][0] = *(const uint32_t*)(rhB + ra * S136 + ka);
            ah[mt][1] = *(const uint32_t*)(rhB + rb * S136 + ka);
            ah[mt][2] = *(const uint32_t*)(rhB + ra * S136 + ka + 8);
            ah[mt][3] = *(const uint32_t*)(rhB + rb * S136 + ka + 8);
            al[mt][0] = *(const uint32_t*)(rlB + ra * S136 + ka);
            al[mt][1] = *(const uint32_t*)(rlB + rb * S136 + ka);
            al[mt][2] = *(const uint32_t*)(rlB + ra * S136 + ka + 8);
            al[mt][3] = *(const uint32_t*)(rlB + rb * S136 + ka + 8);
        }
        // terms 1+2 (W1): per acc order Ah*W1 then Al*W1; interleaved across mt
#pragma unroll
        for (int nt = 0; nt < 4; nt++) {
            int bn = n0 + nt * 8 + gid;
            uint32_t b0 = *(const uint32_t*)(w1B + bn * S136 + ka);
            uint32_t b1 = *(const uint32_t*)(w1B + bn * S136 + ka + 8);
            mma_bf16(acc[0][nt], ah[0][0], ah[0][1], ah[0][2], ah[0][3], b0, b1);
            mma_bf16(acc[1][nt], ah[1][0], ah[1][1], ah[1][2], ah[1][3], b0, b1);
            mma_bf16(acc[0][nt], al[0][0], al[0][1], al[0][2], al[0][3], b0, b1);
            mma_bf16(acc[1][nt], al[1][0], al[1][1], al[1][2], al[1][3], b0, b1);
        }
        // term 3 (W2): Ah*W2
#pragma unroll
        for (int nt = 0; nt < 4; nt++) {
            int bn = n0 + nt * 8 + gid;
            uint32_t c0 = *(const uint32_t*)(w2B + bn * S136 + ka);
            uint32_t c1 = *(const uint32_t*)(w2B + bn * S136 + ka + 8);
            mma_bf16(acc[0][nt], ah[0][0], ah[0][1], ah[0][2], ah[0][3], c0, c1);
            mma_bf16(acc[1][nt], ah[1][0], ah[1][1], ah[1][2], ah[1][3], c0, c1);
        }
    }
}

__global__ __launch_bounds__(512, 1) void k_admm(const float* __restrict__ gQ,
                                                 const float* __restrict__ gV,
                                                 float* __restrict__ gOut) {
    extern __shared__ char smem[];
    __nv_bfloat16* rh0 = (__nv_bfloat16*)(smem + SM_B0H);
    __nv_bfloat16* rl0 = (__nv_bfloat16*)(smem + SM_B0L);
    __nv_bfloat16* rh1 = (__nv_bfloat16*)(smem + SM_B1H);
    __nv_bfloat16* rl1 = (__nv_bfloat16*)(smem + SM_B1L);
    __nv_bfloat16* w1B = (__nv_bfloat16*)(smem + SM_W1);
    __nv_bfloat16* w2B = (__nv_bfloat16*)(smem + SM_W2);
    float* sCnt = (float*)(smem + SM_CNT);

    const int t = threadIdx.x;
    const int lane = t & 31, w = t >> 5;
    const int g = w >> 2;                 // 4 groups of 4 warps
    const int wg2 = w & 3;                // column slice within group
    const int gid = lane >> 2, tig = lane & 3;
    const int m0 = g * 32, n0 = wg2 * 32;
    const int rA = m0 + gid;
    const int b = blockIdx.x >> 4, row0 = (blockIdx.x & 15) * 128;
    const float* Vb = gV + b * 16384;
    const float* Qb = gQ + (size_t)(b * NN + row0) * 128;

    // ---- prologue: Q split -> buf0; V split -> W tiles (float4 loads) ----
    for (int idx = t; idx < 4096; idx += 512) {
        int row = idx >> 5, p4 = (idx & 31) * 4;
        float4 q = *(const float4*)(Qb + row * 128 + p4);
        uint32_t h0, l0, h1, l1;
        split2(q.x, q.y, h0, l0);
        split2(q.z, q.w, h1, l1);
        *(uint2*)(rh0 + row * S136 + p4) = make_uint2(h0, h1);
        *(uint2*)(rl0 + row * S136 + p4) = make_uint2(l0, l1);
        float4 v = *(const float4*)(Vb + row * 128 + p4);
        split2(v.x, v.y, h0, l0);
        split2(v.z, v.w, h1, l1);
        *(uint2*)(w1B + row * S136 + p4) = make_uint2(h0, h1);
        *(uint2*)(w2B + row * S136 + p4) = make_uint2(l0, l1);
    }
    __syncthreads();

    // ---- P = -(2/m) Q V^T + lambda/m -> registers ----
    float P[32];
    {
        float acc[2][4][4];
#pragma unroll
        for (int mt = 0; mt < 2; mt++)
#pragma unroll
            for (int nt = 0; nt < 4; nt++)
#pragma unroll
                for (int j = 0; j < 4; j++) acc[mt][nt][j] = 0.0f;
        gemm3s(acc, rh0, rl0, w1B, w2B, rA, n0, tig, gid);
        const float cP = -2.0f / 128.0f, cL = 0.1f / 128.0f;
#pragma unroll
        for (int mt = 0; mt < 2; mt++)
#pragma unroll
            for (int nt = 0; nt < 4; nt++)
#pragma unroll
                for (int j = 0; j < 4; j++)
                    P[mt * 16 + nt * 4 + j] = cP * acc[mt][nt][j] + cL;
    }
    __syncthreads();   // Q/V tile reads done

    // ---- load W bf16 hi/lo (uint4 vectorized) ----
    {
        const uint4* w1g = (const uint4*)((const uint32_t*)gW1 + b * 8192);
        const uint4* w2g = (const uint4*)((const uint32_t*)gW2 + b * 8192);
        for (int idx = t; idx < 2048; idx += 512) {
            int row = idx >> 4, cw4 = (idx & 15) * 4;
            uint4 v1 = w1g[idx];
            uint4 v2 = w2g[idx];
            *(uint4*)(w1B + row * S136 + cw4 * 2) = v1;
            *(uint4*)(w2B + row * S136 + cw4 * 2) = v2;
        }
    }

    float xu[32];
#pragma unroll
    for (int e = 0; e < 32; e++) xu[e] = 0.0f;

    // initial rhs (it=0): z=u=0 -> (0-0)-P, into buf0
#pragma unroll
    for (int mt = 0; mt < 2; mt++) {
        int ra = rA + 16 * mt, rb = ra + 8;
#pragma unroll
        for (int nt = 0; nt < 4; nt++) {
            int e = mt * 16 + nt * 4;
            int c = n0 + nt * 8 + 2 * tig;
            uint32_t hi, lo;
            split2((0.0f - 0.0f) - P[e], (0.0f - 0.0f) - P[e + 1], hi, lo);
            *(uint32_t*)(rh0 + ra * S136 + c) = hi;
            *(uint32_t*)(rl0 + ra * S136 + c) = lo;
            split2((0.0f - 0.0f) - P[e + 2], (0.0f - 0.0f) - P[e + 3], hi, lo);
            *(uint32_t*)(rh0 + rb * S136 + c) = hi;
            *(uint32_t*)(rl0 + rb * S136 + c) = lo;
        }
    }
    __syncthreads();   // covers W load + initial rhs

    // ---- 50 ADMM iterations; last iteration skips the dead rhs store+barrier ----
    for (int it = 0; it < ITERS; it++) {
        const __nv_bfloat16* rhR = (it & 1) ? rh1 : rh0;
        const __nv_bfloat16* rlR = (it & 1) ? rl1 : rl0;
        __nv_bfloat16* rhW = (it & 1) ? rh0 : rh1;
        __nv_bfloat16* rlW = (it & 1) ? rl0 : rl1;

        float acc[2][4][4];
#pragma unroll
        for (int mt = 0; mt < 2; mt++)
#pragma unroll
            for (int nt = 0; nt < 4; nt++)
#pragma unroll
                for (int j = 0; j < 4; j++) acc[mt][nt][j] = 0.0f;
        gemm3s(acc, rhR, rlR, w1B, w2B, rA, n0, tig, gid);

        if (it == ITERS - 1) {
            // final pointwise update only (stored rhs would never be read)
#pragma unroll
            for (int mt = 0; mt < 2; mt++)
#pragma unroll
                for (int nt = 0; nt < 4; nt++)
#pragma unroll
                    for (int j = 0; j < 4; j++) {
                        int ee = mt * 16 + nt * 4 + j;
                        float zd = fminf(fmaxf(xu[ee], 0.0f), 1.0f);
                        float ud = xu[ee] - zd;
                        float rhs = (zd - ud) - P[ee];
                        float x = rhs + acc[mt][nt][j];
                        xu[ee] = x + ud;
                    }
            break;
        }

#pragma unroll
        for (int mt = 0; mt < 2; mt++) {
            int ra = rA + 16 * mt, rb = ra + 8;
#pragma unroll
            for (int nt = 0; nt < 4; nt++) {
                int e = mt * 16 + nt * 4;
                int c = n0 + nt * 8 + 2 * tig;
                float r4[4];
#pragma unroll
                for (int j = 0; j < 4; j++) {
                    int ee = e + j;
                    float zd = fminf(fmaxf(xu[ee], 0.0f), 1.0f);
                    float ud = xu[ee] - zd;
                    float rhs = (zd - ud) - P[ee];
                    float x = rhs + acc[mt][nt][j];
                    xu[ee] = x + ud;
                    float zd2 = fminf(fmaxf(xu[ee], 0.0f), 1.0f);
                    float ud2 = xu[ee] - zd2;
                    r4[j] = (zd2 - ud2) - P[ee];
                }
                uint32_t hi, lo;
                split2(r4[0], r4[1], hi, lo);
                *(uint32_t*)(rhW + ra * S136 + c) = hi;
                *(uint32_t*)(rlW + ra * S136 + c) = lo;
                split2(r4[2], r4[3], hi, lo);
                *(uint32_t*)(rhW + rb * S136 + c) = hi;
                *(uint32_t*)(rlW + rb * S136 + c) = lo;
            }
        }
        barg128(1 + g);
    }

    // ---- epilogue: counts, coeffs, out = coeff * (V/128) ----
    float z[32];
#pragma unroll
    for (int e = 0; e < 32; e++) z[e] = fminf(fmaxf(xu[e], 0.0f), 1.0f);
#pragma unroll
    for (int mt = 0; mt < 2; mt++) {
        int ra = rA + 16 * mt, rb = ra + 8;
        float c0s = 0.0f, c1s = 0.0f;
#pragma unroll
        for (int nt = 0; nt < 4; nt++) {
            int e = mt * 16 + nt * 4;
            c0s += ((z[e]     > 0.5f) ? 1.0f : 0.0f) + ((z[e + 1] > 0.5f) ? 1.0f : 0.0f);
            c1s += ((z[e + 2] > 0.5f) ? 1.0f : 0.0f) + ((z[e + 3] > 0.5f) ? 1.0f : 0.0f);
        }
        sCnt[ra * 16 + wg2 * 4 + tig] = c0s;
        sCnt[rb * 16 + wg2 * 4 + tig] = c1s;
    }
    barg128(1 + g);
    float inv[2][2];
#pragma unroll
    for (int mt = 0; mt < 2; mt++) {
        int ra = rA + 16 * mt, rb = ra + 8;
        float s0 = 0.0f, s1 = 0.0f;
#pragma unroll
        for (int k = 0; k < 16; k++) { s0 += sCnt[ra * 16 + k]; s1 += sCnt[rb * 16 + k]; }
        inv[mt][0] = 1.0f / (128.0f * (s0 + 1e-10f));
        inv[mt][1] = 1.0f / (128.0f * (s1 + 1e-10f));
    }
#pragma unroll
    for (int mt = 0; mt < 2; mt++) {
        int ra = rA + 16 * mt, rb = ra + 8;
#pragma unroll
        for (int nt = 0; nt < 4; nt++) {
            int e = mt * 16 + nt * 4;
            int c = n0 + nt * 8 + 2 * tig;
            uint32_t hi, lo;
            split2((z[e]     > 0.5f) ? inv[mt][0] : 0.0f,
                   (z[e + 1] > 0.5f) ? inv[mt][0] : 0.0f, hi, lo);
            *(uint32_t*)(rh0 + ra * S136 + c) = hi;
            *(uint32_t*)(rl0 + ra * S136 + c) = lo;
            split2((z[e + 2] > 0.5f) ? inv[mt][1] : 0.0f,
                   (z[e + 3] > 0.5f) ? inv[mt][1] : 0.0f, hi, lo);
            *(uint32_t*)(rh0 + rb * S136 + c) = hi;
            *(uint32_t*)(rl0 + rb * S136 + c) = lo;
        }
    }
    __syncthreads();   // all groups done with W tiles + coeff writes
    for (int idx = t; idx < 16384; idx += 512) {
        int m = idx >> 7, d = idx & 127;
        float f = Vb[idx];
        __nv_bfloat16 h = __float2bfloat16(f);
        w1B[d * S136 + m] = h;
        w2B[d * S136 + m] = __float2bfloat16(f - __bfloat162float(h));
    }
    __syncthreads();

    {
        float acc[2][4][4];
#pragma unroll
        for (int mt = 0; mt < 2; mt++)
#pragma unroll
            for (int nt = 0; nt < 4; nt++)
#pragma unroll
                for (int j = 0; j < 4; j++) acc[mt][nt][j] = 0.0f;
        gemm3s(acc, rh0, rl0, w1B, w2B, rA, n0, tig, gid);
        float* ob = gOut + (size_t)(b * NN + row0) * 128;
#pragma unroll
        for (int mt = 0; mt < 2; mt++) {
            int ra = rA + 16 * mt, rb = ra + 8;
#pragma unroll
            for (int nt = 0; nt < 4; nt++) {
                int c = n0 + nt * 8 + 2 * tig;
                *(float2*)(ob + ra * 128 + c) = make_float2(acc[mt][nt][0], acc[mt][nt][1]);
                *(float2*)(ob + rb * 128 + c) = make_float2(acc[mt][nt][2], acc[mt][nt][3]);
            }
        }
    }
}

// ============================================================================

extern "C" void kernel_launch(void* const* d_in, const int* in_sizes, int n_in,
                              void* d_out, int out_size) {
    const float* gQ = (const float*)d_in[0];
    const float* gV = (const float*)d_in[1];
    if (n_in >= 2 && in_sizes[0] == BB * 128 * 128 && in_sizes[1] == BB * NN * 128) {
        gV = (const float*)d_in[0];
        gQ = (const float*)d_in[1];
    }
    float* out = (float*)d_out;

    const int SMEM_E   = 128 * 132 * 4;                // 67584
    const int SMEM_MM1 = (8 * 129 + 128 * 128) * 4;    // 69664
    const int SMEM_MM2 = (16 * 129 + 128 * 128) * 4;   // 73792

    cudaFuncSetAttribute(kE,   cudaFuncAttributeMaxDynamicSharedMemorySize, SMEM_E);
    cudaFuncSetAttribute(kMM1, cudaFuncAttributeMaxDynamicSharedMemorySize, SMEM_MM1);
    cudaFuncSetAttribute(kMM2, cudaFuncAttributeMaxDynamicSharedMemorySize, SMEM_MM2);
    cudaFuncSetAttribute(k_admm, cudaFuncAttributeMaxDynamicSharedMemorySize, SMEM_ADMM);

    kE<<<128, 256, SMEM_E>>>(gV);
    kMM1<<<128, 256, SMEM_MM1>>>();       // E2 = E*E ; S = I - E + E2
    kMM2<<<128, 256, SMEM_MM2>>>();       // W = E2*S - E -> bf16 hi/lo
    k_admm<<<BB * (NN / 128), 512, SMEM_ADMM>>>(gQ, gV, out);
}